// round 6
// baseline (speedup 1.0000x reference)
#include <cuda_runtime.h>

#define NBLK 1184             // 148 SMs * 8 blocks
#define NTHR 256
#define STRIDE ((long)NBLK * NTHR)

__device__ float                 g_partials[NBLK];
__device__ volatile float        g_scale_v;
__device__ unsigned int          g_count  = 0;
__device__ unsigned int          g_count2 = 0;
__device__ volatile unsigned int g_ready  = 0;

__device__ __forceinline__ float warp_reduce_f(float v) {
    #pragma unroll
    for (int o = 16; o > 0; o >>= 1) v += __shfl_xor_sync(0xffffffffu, v, o);
    return v;
}
__device__ __forceinline__ double warp_reduce_d(double v) {
    #pragma unroll
    for (int o = 16; o > 0; o >>= 1) v += __shfl_xor_sync(0xffffffffu, v, o);
    return v;
}
__device__ __forceinline__ float sq4(float4 v, float acc) {
    acc = fmaf(v.x, v.x, acc);
    acc = fmaf(v.y, v.y, acc);
    acc = fmaf(v.z, v.z, acc);
    acc = fmaf(v.w, v.w, acc);
    return acc;
}

__global__ void __launch_bounds__(NTHR, 8)
clip_fused_kernel(const float4* __restrict__ p0, long n0, long o0,
                  const float4* __restrict__ p1, long n1, long o1,
                  const float4* __restrict__ p2, long n2, long o2,
                  const float4* __restrict__ p3, long n3, long o3,
                  const float4* __restrict__ p4, long n4, long o4,
                  float4* __restrict__ out)
{
    const long tid = (long)blockIdx.x * NTHR + threadIdx.x;

    const float4* ps[5] = {p0, p1, p2, p3, p4};
    long          ns[5] = {n0, n1, n2, n3, n4};
    long          os[5] = {o0, o1, o2, o3, o4};

    // ---------------- Phase 1: sum of squares (forward sweep) ----------------
    float acc = 0.0f;
    #pragma unroll
    for (int t = 0; t < 5; t++) {
        const float4* __restrict__ p = ps[t];
        const long n = ns[t];
        long i = tid;
        for (; i + 3 * STRIDE < n; i += 4 * STRIDE) {
            float4 v0 = p[i];
            float4 v1 = p[i + STRIDE];
            float4 v2 = p[i + 2 * STRIDE];
            float4 v3 = p[i + 3 * STRIDE];
            acc = sq4(v0, acc);
            acc = sq4(v1, acc);
            acc = sq4(v2, acc);
            acc = sq4(v3, acc);
        }
        for (; i < n; i += STRIDE)
            acc = sq4(p[i], acc);
    }

    // block reduce
    acc = warp_reduce_f(acc);
    __shared__ float sm[NTHR / 32];
    if ((threadIdx.x & 31) == 0) sm[threadIdx.x >> 5] = acc;
    __syncthreads();
    if (threadIdx.x < 32) {
        float v = (threadIdx.x < NTHR / 32) ? sm[threadIdx.x] : 0.0f;
        v = warp_reduce_f(v);
        if (threadIdx.x == 0) g_partials[blockIdx.x] = v;
    }

    // ---------------- Grid barrier + finalize (last block) -------------------
    __shared__ bool  sh_last;
    __shared__ float sh_scale;
    if (threadIdx.x == 0) {
        __threadfence();   // publish g_partials[blockIdx.x]
        unsigned prev = atomicAdd(&g_count, 1u);
        sh_last = (prev == NBLK - 1u);
    }
    __syncthreads();

    if (sh_last) {
        // whole last block reduces the 1184 partials in double (fixed order)
        double d = 0.0;
        for (int i = threadIdx.x; i < NBLK; i += NTHR)
            d += (double)g_partials[i];
        d = warp_reduce_d(d);
        __shared__ double sd[NTHR / 32];
        if ((threadIdx.x & 31) == 0) sd[threadIdx.x >> 5] = d;
        __syncthreads();
        if (threadIdx.x < 32) {
            double v = (threadIdx.x < NTHR / 32) ? sd[threadIdx.x] : 0.0;
            v = warp_reduce_d(v);
            if (threadIdx.x == 0) {
                float norm = sqrtf((float)v);
                g_scale_v = (norm > 1.0f) ? (1.0f / (norm + 1e-6f)) : 1.0f;
                __threadfence();
                g_ready = 1u;
            }
        }
    }

    // all blocks: thread0 spins until scale is published
    if (threadIdx.x == 0) {
        while (g_ready == 0u) { __nanosleep(64); }
        __threadfence();
        sh_scale = g_scale_v;
        // self-reset for next graph replay: last thread through resets state
        unsigned prev2 = atomicAdd(&g_count2, 1u);
        if (prev2 == NBLK - 1u) {
            g_count  = 0u;
            g_ready  = 0u;
            __threadfence();
            g_count2 = 0u;
        }
    }
    __syncthreads();
    const float s = sh_scale;

    // ---------------- Phase 2: scale (each thread revisits ITS OWN ----------
    // ---------------- phase-1 indices in reverse => L1 + L2 hits) -----------
    #pragma unroll
    for (int t = 4; t >= 0; t--) {
        const float4* __restrict__ p = ps[t];
        float4* __restrict__ q = out + os[t];
        const long n = ns[t];
        long cnt = (tid < n) ? ((n - 1 - tid) / STRIDE + 1) : 0;
        long i = tid + (cnt - 1) * STRIDE;
        for (long m = 0; m < cnt; m++, i -= STRIDE) {
            float4 v = __ldcs(&p[i]);
            v.x *= s; v.y *= s; v.z *= s; v.w *= s;
            __stcs(&q[i], v);
        }
    }
}

extern "C" void kernel_launch(void* const* d_in, const int* in_sizes, int n_in,
                              void* d_out, int out_size)
{
    const float* g[5];
    long n[5];
    for (int i = 0; i < 5; i++) {
        g[i] = (const float*)d_in[i];
        n[i] = (long)in_sizes[i];
    }
    long n4[5], off4[5];
    long cum = 0;
    for (int i = 0; i < 5; i++) {
        n4[i]   = n[i] >> 2;   // float4 count (all shapes divisible by 4)
        off4[i] = cum >> 2;
        cum += n[i];
    }

    clip_fused_kernel<<<NBLK, NTHR>>>(
        (const float4*)g[0], n4[0], off4[0],
        (const float4*)g[1], n4[1], off4[1],
        (const float4*)g[2], n4[2], off4[2],
        (const float4*)g[3], n4[3], off4[3],
        (const float4*)g[4], n4[4], off4[4],
        (float4*)d_out);
}